// round 12
// baseline (speedup 1.0000x reference)
#include <cuda_runtime.h>
#include <cuda_bf16.h>
#include <cuda_fp16.h>
#include <cstdint>

#define N_NODES 10000
#define N_EDGES 640000
#define F_IN    128
#define F_OUT   512

// ---------------- device scratch ----------------
// blob layout: [0]=barrier count, [1]=barrier gen, [2]=alloc cursor,
//              [3 .. 3+N)   = deg
//              [3+N .. end) = csr
// One memset zeroes barrier state, cursor, deg, and pre-touches csr.
__device__ int g_blob[3 + N_NODES + N_EDGES];
#define G_CNT   (*(unsigned*)&g_blob[0])
#define G_GEN   (*(volatile unsigned*)&g_blob[1])
#define G_TOTAL g_blob[2]
#define G_DEG(i) g_blob[3 + (i)]
#define G_CSR(i) g_blob[3 + N_NODES + (i)]
__device__ int g_off[N_NODES];
__device__ int g_rank[N_EDGES];
__device__ __align__(16) __half g_x16[N_NODES * F_IN];
__device__ __align__(16) unsigned short g_hh[N_NODES * F_IN];
__device__ __align__(16) unsigned short g_hl[N_NODES * F_IN];
__device__ __align__(16) unsigned short g_wt_hi[F_OUT * F_IN];
__device__ __align__(16) unsigned short g_wt_lo[F_OUT * F_IN];

__device__ __forceinline__ void split_bf16(float v, unsigned short& h, unsigned short& l) {
    __nv_bfloat16 bh = __float2bfloat16(v);
    __nv_bfloat16 bl = __float2bfloat16(v - __bfloat162float(bh));
    h = __bfloat16_as_ushort(bh);
    l = __bfloat16_as_ushort(bl);
}

// software grid barrier: all blocks resident (guaranteed by launch_bounds + grid size)
__device__ __forceinline__ void gbar(int nb) {
    __syncthreads();
    if (threadIdx.x == 0) {
        __threadfence();                       // release prior writes
        unsigned gen = G_GEN;
        if (atomicAdd(&G_CNT, 1u) == (unsigned)(nb - 1)) {
            G_CNT = 0;
            __threadfence();
            G_GEN = gen + 1;
        } else {
            while (G_GEN == gen) { __nanosleep(64); }
        }
        __threadfence();                       // acquire
    }
    __syncthreads();
}

#define XCONV_ITEMS (N_NODES * F_IN / 4)      // 320000 float4s
#define WCONV_ITEMS (F_OUT * F_IN)            // 65536 elements

// ---------------- mega kernel: conv+deg -> off -> fill -> gather -------------
__global__ void __launch_bounds__(256, 2)
k_mega(const float* __restrict__ x, const float* __restrict__ W,
       const int* __restrict__ src, const int* __restrict__ dst, int nb) {
    int tid0 = blockIdx.x * 256 + threadIdx.x;
    int stride = nb * 256;
    int lane = threadIdx.x & 31;

    // ---- phase 0: x->fp16, W->transposed bf16 hi/lo, deg+rank (independent) ----
    for (int i = tid0; i < XCONV_ITEMS; i += stride) {
        float4 v = ((const float4*)x)[i];
        __half2 a = __floats2half2_rn(v.x, v.y);
        __half2 b = __floats2half2_rn(v.z, v.w);
        ((uint2*)g_x16)[i] = make_uint2(*(uint32_t*)&a, *(uint32_t*)&b);
    }
    for (int idx = tid0; idx < WCONV_ITEMS; idx += stride) {
        int n = idx >> 7, k = idx & 127;
        float v = W[(size_t)k * F_OUT + n];
        unsigned short h, l;
        split_bf16(v, h, l);
        g_wt_hi[idx] = h;
        g_wt_lo[idx] = l;
    }
    for (int t = tid0; t < N_EDGES / 8; t += stride) {
        int e = t * 8;
        int4 a = *(const int4*)&dst[e];
        int4 b = *(const int4*)&dst[e + 4];
        int r0 = atomicAdd(&G_DEG(a.x), 1);
        int r1 = atomicAdd(&G_DEG(a.y), 1);
        int r2 = atomicAdd(&G_DEG(a.z), 1);
        int r3 = atomicAdd(&G_DEG(a.w), 1);
        int r4 = atomicAdd(&G_DEG(b.x), 1);
        int r5 = atomicAdd(&G_DEG(b.y), 1);
        int r6 = atomicAdd(&G_DEG(b.z), 1);
        int r7 = atomicAdd(&G_DEG(b.w), 1);
        *(int4*)&g_rank[e]     = make_int4(r0, r1, r2, r3);
        *(int4*)&g_rank[e + 4] = make_int4(r4, r5, r6, r7);
    }
    gbar(nb);

    // ---- phase 1: segment allocation (warp-aggregated cursor); single pass ----
    {
        int i = tid0;       // stride >= N_NODES guaranteed (nb*256 >= 10000)
        int d = (i < N_NODES) ? G_DEG(i) : 0;
        int inc = d;
#pragma unroll
        for (int o = 1; o < 32; o <<= 1) {
            int v = __shfl_up_sync(~0u, inc, o);
            if (lane >= o) inc += v;
        }
        int wsum = __shfl_sync(~0u, inc, 31);
        int base = 0;
        if (lane == 31 && wsum > 0) base = atomicAdd(&G_TOTAL, wsum);
        base = __shfl_sync(~0u, base, 31);
        if (i < N_NODES) g_off[i] = base + inc - d;
    }
    gbar(nb);

    // ---- phase 2: fill CSR (atomic-free) ----
    for (int t = tid0; t < N_EDGES / 8; t += stride) {
        int e = t * 8;
        int4 da = *(const int4*)&dst[e];
        int4 db = *(const int4*)&dst[e + 4];
        int4 sa = *(const int4*)&src[e];
        int4 sb = *(const int4*)&src[e + 4];
        int4 ra = *(const int4*)&g_rank[e];
        int4 rb = *(const int4*)&g_rank[e + 4];
        G_CSR(g_off[da.x] + ra.x) = sa.x;
        G_CSR(g_off[da.y] + ra.y) = sa.y;
        G_CSR(g_off[da.z] + ra.z) = sa.z;
        G_CSR(g_off[da.w] + ra.w) = sa.w;
        G_CSR(g_off[db.x] + rb.x) = sb.x;
        G_CSR(g_off[db.y] + rb.y) = sb.y;
        G_CSR(g_off[db.z] + rb.z) = sb.z;
        G_CSR(g_off[db.w] + rb.w) = sb.w;
    }
    gbar(nb);

    // ---- phase 3: gather-mean (fp16 reads) -> bf16 hi/lo rows ----
    const uint2* __restrict__ x2 = (const uint2*)g_x16;
    int nwarps = stride >> 5;
    for (int gw = tid0 >> 5; gw < N_NODES; gw += nwarps) {
        int d = G_DEG(gw);
        int beg = g_off[gw];
        int end = beg + d;

        float ax = 0.f, ay = 0.f, az = 0.f, aw = 0.f;
        int j = beg;
        for (; j + 7 < end; j += 8) {
            int s0 = G_CSR(j + 0), s1 = G_CSR(j + 1), s2 = G_CSR(j + 2), s3 = G_CSR(j + 3);
            int s4 = G_CSR(j + 4), s5 = G_CSR(j + 5), s6 = G_CSR(j + 6), s7 = G_CSR(j + 7);
            uint2 c0 = x2[s0 * 32 + lane];
            uint2 c1 = x2[s1 * 32 + lane];
            uint2 c2 = x2[s2 * 32 + lane];
            uint2 c3 = x2[s3 * 32 + lane];
            uint2 c4 = x2[s4 * 32 + lane];
            uint2 c5 = x2[s5 * 32 + lane];
            uint2 c6 = x2[s6 * 32 + lane];
            uint2 c7 = x2[s7 * 32 + lane];
#define ACC(c)                                                     \
            {                                                      \
                float2 f0 = __half22float2(*(__half2*)&(c).x);     \
                float2 f1 = __half22float2(*(__half2*)&(c).y);     \
                ax += f0.x; ay += f0.y; az += f1.x; aw += f1.y;    \
            }
            ACC(c0) ACC(c1) ACC(c2) ACC(c3) ACC(c4) ACC(c5) ACC(c6) ACC(c7)
        }
        for (; j < end; ++j) {
            int s = G_CSR(j);
            uint2 c = x2[s * 32 + lane];
            ACC(c)
        }
#undef ACC

        float4 o;
        if (d > 0) {
            float inv = 1.0f / (float)d;
            o.x = ax * inv; o.y = ay * inv; o.z = az * inv; o.w = aw * inv;
        } else {
            o = ((const float4*)x)[gw * 32 + lane];   // exact fp32 fallback
        }

        unsigned short h0, h1, h2, h3, l0, l1, l2, l3;
        split_bf16(o.x, h0, l0);
        split_bf16(o.y, h1, l1);
        split_bf16(o.z, h2, l2);
        split_bf16(o.w, h3, l3);
        uint2 hv = make_uint2(((uint32_t)h1 << 16) | h0, ((uint32_t)h3 << 16) | h2);
        uint2 lv = make_uint2(((uint32_t)l1 << 16) | l0, ((uint32_t)l3 << 16) | l2);
        int base = gw * F_IN + lane * 4;
        *(uint2*)&g_hh[base] = hv;
        *(uint2*)&g_hl[base] = lv;
    }
}

// ---------------- mma.sync bf16 GEMM: A-tile resident, loop over N-chunks ----
#define GBM 128
#define NCHUNKS 4
#define APITCH 528
#define A_BYTES (128 * APITCH)
#define GEMM_SMEM_BYTES (2 * A_BYTES + 256)

__device__ __forceinline__ uint32_t smem_u32(const void* p) {
    uint32_t a;
    asm("{ .reg .u64 t; cvta.to.shared.u64 t, %1; cvt.u32.u64 %0, t; }"
        : "=r"(a) : "l"(p));
    return a;
}

#define LDMX4(r0, r1, r2, r3, addr)                                             \
    asm volatile("ldmatrix.sync.aligned.m8n8.x4.shared.b16 {%0,%1,%2,%3}, [%4];" \
                 : "=r"(r0), "=r"(r1), "=r"(r2), "=r"(r3) : "r"(addr))

#define MMA16816(c, a0, a1, a2, a3, b0, b1)                                     \
    asm volatile("mma.sync.aligned.m16n8k16.row.col.f32.bf16.bf16.f32 "         \
                 "{%0,%1,%2,%3}, {%4,%5,%6,%7}, {%8,%9}, {%0,%1,%2,%3};"        \
                 : "+f"((c)[0]), "+f"((c)[1]), "+f"((c)[2]), "+f"((c)[3])       \
                 : "r"(a0), "r"(a1), "r"(a2), "r"(a3), "r"(b0), "r"(b1))

__global__ void __launch_bounds__(256, 1)
k_gemm_mma(const float* __restrict__ bias, float* __restrict__ out) {
    extern __shared__ char smem_raw[];
    uint32_t sb0 = smem_u32(smem_raw);
    uint32_t ab = (sb0 + 255) & ~255u;
    char* tb = smem_raw + (ab - sb0);
    const uint32_t B_OFF = A_BYTES;

    int tid = threadIdx.x;
    int wid = tid >> 5, lane = tid & 31;
    int warp_m = wid & 3;
    int warp_n = wid >> 2;
    int m0 = blockIdx.x * GBM;

    const uint4* __restrict__ hh4 = (const uint4*)g_hh;
    const uint4* __restrict__ hl4 = (const uint4*)g_hl;
    for (int i = tid; i < 128 * 16; i += 256) {
        int m = i >> 4;
        int c = i & 15;
        uint4 hv, lv;
        if (m0 + m < N_NODES) {
            hv = hh4[(size_t)(m0 + m) * 16 + c];
            lv = hl4[(size_t)(m0 + m) * 16 + c];
        } else {
            hv = make_uint4(0, 0, 0, 0);
            lv = make_uint4(0, 0, 0, 0);
        }
        char* row = tb + m * APITCH + c * 16;
        *(uint4*)(row) = hv;
        *(uint4*)(row + 256) = lv;
    }

    const uint4* __restrict__ wh4 = (const uint4*)g_wt_hi;
    const uint4* __restrict__ wl4 = (const uint4*)g_wt_lo;

    int a_row = (lane & 15);
    int a_koff = (lane >> 4) << 4;
    int b_nrow = ((lane >> 4) << 3) + (lane & 7);
    int b_koff = ((lane >> 3) & 1) << 4;
    int g = lane >> 2;
    int t = lane & 3;

    for (int nc = 0; nc < NCHUNKS; nc++) {
        int n0 = nc * 128;
        __syncthreads();
        for (int i = tid; i < 128 * 16; i += 256) {
            int n = i >> 4;
            int c = i & 15;
            uint4 hv = wh4[(size_t)(n0 + n) * 16 + c];
            uint4 lv = wl4[(size_t)(n0 + n) * 16 + c];
            char* row = tb + B_OFF + n * APITCH + c * 16;
            *(uint4*)(row) = hv;
            *(uint4*)(row + 256) = lv;
        }
        __syncthreads();

        float acc[2][8][4] = {};

#pragma unroll
        for (int pass = 0; pass < 3; pass++) {
            uint32_t abase = (pass < 2) ? 0u : 256u;
            uint32_t bbase = (pass == 1) ? 256u : 0u;
#pragma unroll
            for (int kk = 0; kk < 8; kk++) {
                uint32_t kb = kk * 32;
                uint32_t a0, a1, a2, a3, a4, a5, a6, a7;
                {
                    uint32_t addr0 = ab + (uint32_t)((warp_m * 32 + a_row) * APITCH) +
                                     abase + kb + a_koff;
                    uint32_t addr1 = addr0 + 16 * APITCH;
                    LDMX4(a0, a1, a2, a3, addr0);
                    LDMX4(a4, a5, a6, a7, addr1);
                }
#pragma unroll
                for (int nt2 = 0; nt2 < 4; nt2++) {
                    uint32_t baddr = ab + B_OFF +
                                     (uint32_t)((warp_n * 64 + nt2 * 16 + b_nrow) * APITCH) +
                                     bbase + kb + b_koff;
                    uint32_t b0, b1, b2, b3;
                    LDMX4(b0, b1, b2, b3, baddr);
                    MMA16816(acc[0][nt2 * 2 + 0], a0, a1, a2, a3, b0, b1);
                    MMA16816(acc[1][nt2 * 2 + 0], a4, a5, a6, a7, b0, b1);
                    MMA16816(acc[0][nt2 * 2 + 1], a0, a1, a2, a3, b2, b3);
                    MMA16816(acc[1][nt2 * 2 + 1], a4, a5, a6, a7, b2, b3);
                }
            }
        }

#pragma unroll
        for (int mt = 0; mt < 2; mt++) {
            int row0 = m0 + warp_m * 32 + mt * 16 + g;
            int row1 = row0 + 8;
#pragma unroll
            for (int nt = 0; nt < 8; nt++) {
                int col = n0 + warp_n * 64 + nt * 8 + t * 2;
                float2 bv = *(const float2*)&bias[col];
                if (row0 < N_NODES) {
                    float2 o = make_float2(acc[mt][nt][0] + bv.x, acc[mt][nt][1] + bv.y);
                    *(float2*)&out[(size_t)row0 * F_OUT + col] = o;
                }
                if (row1 < N_NODES) {
                    float2 o = make_float2(acc[mt][nt][2] + bv.x, acc[mt][nt][3] + bv.y);
                    *(float2*)&out[(size_t)row1 * F_OUT + col] = o;
                }
            }
        }
    }
}

// ---------------- launch ----------------
extern "C" void kernel_launch(void* const* d_in, const int* in_sizes, int n_in,
                              void* d_out, int out_size) {
    const float* x   = (const float*)d_in[0];
    const int*   src = (const int*)d_in[1];
    const int*   dst = (const int*)d_in[2];
    const float* W   = (const float*)d_in[3];
    const float* b   = (const float*)d_in[4];
    float* out = (float*)d_out;

    cudaFuncSetAttribute(k_gemm_mma, cudaFuncAttributeMaxDynamicSharedMemorySize,
                         GEMM_SMEM_BYTES);

    int nsm = 148;
    cudaDeviceGetAttribute(&nsm, cudaDevAttrMultiProcessorCount, 0);
    int nb = nsm * 2;   // __launch_bounds__(256,2) guarantees co-residency

    void* blobp = nullptr;
    cudaGetSymbolAddress(&blobp, g_blob);
    cudaMemsetAsync(blobp, 0, sizeof(int) * (3 + N_NODES + N_EDGES));

    k_mega<<<nb, 256>>>(x, W, src, dst, nb);
    k_gemm_mma<<<(N_NODES + GBM - 1) / GBM, 256, GEMM_SMEM_BYTES>>>(b, out);
}

// round 13
// speedup vs baseline: 1.1134x; 1.1134x over previous
#include <cuda_runtime.h>
#include <cuda_bf16.h>
#include <cuda_fp16.h>
#include <cstdint>

#define N_NODES 10000
#define N_EDGES 640000
#define F_IN    128
#define F_OUT   512

// ---------------- device scratch ----------------
__device__ int   g_deg[N_NODES];
__device__ int   g_off[N_NODES];
__device__ int   g_total;
__device__ int   g_rank[N_EDGES];
__device__ int   g_csr[N_EDGES];
__device__ __align__(16) __half g_x16[N_NODES * F_IN];
__device__ __align__(16) unsigned short g_hh[N_NODES * F_IN];
__device__ __align__(16) unsigned short g_hl[N_NODES * F_IN];
__device__ __align__(16) unsigned short g_wt_hi[F_OUT * F_IN];
__device__ __align__(16) unsigned short g_wt_lo[F_OUT * F_IN];

__device__ __forceinline__ void split_bf16(float v, unsigned short& h, unsigned short& l) {
    __nv_bfloat16 bh = __float2bfloat16(v);
    __nv_bfloat16 bl = __float2bfloat16(v - __bfloat162float(bh));
    h = __bfloat16_as_ushort(bh);
    l = __bfloat16_as_ushort(bl);
}

// ---------------- fused conversions ----------------
#define XCONV_ITEMS (N_NODES * F_IN / 4)
#define WCONV_ITEMS (F_OUT * F_IN)
__global__ void k_conv(const float* __restrict__ x, const float* __restrict__ W) {
    int i = blockIdx.x * blockDim.x + threadIdx.x;
    if (i == 0) g_total = 0;
    if (i < XCONV_ITEMS) {
        float4 v = ((const float4*)x)[i];
        __half2 a = __floats2half2_rn(v.x, v.y);
        __half2 b = __floats2half2_rn(v.z, v.w);
        ((uint2*)g_x16)[i] = make_uint2(*(uint32_t*)&a, *(uint32_t*)&b);
    } else {
        int idx = i - XCONV_ITEMS;
        if (idx < WCONV_ITEMS) {
            int n = idx >> 7, k = idx & 127;
            float v = W[(size_t)k * F_OUT + n];
            unsigned short h, l;
            split_bf16(v, h, l);
            g_wt_hi[idx] = h;
            g_wt_lo[idx] = l;
        }
    }
}

// ---------------- deg + rank (8 edges/thread) ----------------
__global__ void k_deg(const int* __restrict__ dst) {
    int t = blockIdx.x * blockDim.x + threadIdx.x;
    int e = t * 8;
    if (e < N_EDGES) {
        int4 a = *(const int4*)&dst[e];
        int4 b = *(const int4*)&dst[e + 4];
        int r0 = atomicAdd(&g_deg[a.x], 1);
        int r1 = atomicAdd(&g_deg[a.y], 1);
        int r2 = atomicAdd(&g_deg[a.z], 1);
        int r3 = atomicAdd(&g_deg[a.w], 1);
        int r4 = atomicAdd(&g_deg[b.x], 1);
        int r5 = atomicAdd(&g_deg[b.y], 1);
        int r6 = atomicAdd(&g_deg[b.z], 1);
        int r7 = atomicAdd(&g_deg[b.w], 1);
        *(int4*)&g_rank[e]     = make_int4(r0, r1, r2, r3);
        *(int4*)&g_rank[e + 4] = make_int4(r4, r5, r6, r7);
    }
}

// ---------------- segment allocation ----------------
__global__ void k_off() {
    int i = blockIdx.x * blockDim.x + threadIdx.x;
    int lane = threadIdx.x & 31;
    int d = (i < N_NODES) ? g_deg[i] : 0;
    int inc = d;
#pragma unroll
    for (int o = 1; o < 32; o <<= 1) {
        int v = __shfl_up_sync(~0u, inc, o);
        if (lane >= o) inc += v;
    }
    int wsum = __shfl_sync(~0u, inc, 31);
    int base = 0;
    if (lane == 31) base = atomicAdd(&g_total, wsum);
    base = __shfl_sync(~0u, base, 31);
    if (i < N_NODES) g_off[i] = base + inc - d;
}

// ---------------- fill CSR ----------------
__global__ void k_fill(const int* __restrict__ src, const int* __restrict__ dst) {
    int t = blockIdx.x * blockDim.x + threadIdx.x;
    int e = t * 8;
    if (e < N_EDGES) {
        int4 da = *(const int4*)&dst[e];
        int4 db = *(const int4*)&dst[e + 4];
        int4 sa = *(const int4*)&src[e];
        int4 sb = *(const int4*)&src[e + 4];
        int4 ra = *(const int4*)&g_rank[e];
        int4 rb = *(const int4*)&g_rank[e + 4];
        g_csr[g_off[da.x] + ra.x] = sa.x;
        g_csr[g_off[da.y] + ra.y] = sa.y;
        g_csr[g_off[da.z] + ra.z] = sa.z;
        g_csr[g_off[da.w] + ra.w] = sa.w;
        g_csr[g_off[db.x] + rb.x] = sb.x;
        g_csr[g_off[db.y] + rb.y] = sb.y;
        g_csr[g_off[db.z] + rb.z] = sb.z;
        g_csr[g_off[db.w] + rb.w] = sb.w;
    }
}

// ---------------- gather-mean (fp16 reads) -> bf16 hi/lo rows ----------------
__global__ void k_gather(const float* __restrict__ x) {
    int gw = (blockIdx.x * blockDim.x + threadIdx.x) >> 5;
    int lane = threadIdx.x & 31;
    if (gw >= N_NODES) return;

    const uint2* __restrict__ x2 = (const uint2*)g_x16;
    int d = g_deg[gw];
    int beg = g_off[gw];
    int end = beg + d;

    float ax = 0.f, ay = 0.f, az = 0.f, aw = 0.f;
    int j = beg;
    for (; j + 7 < end; j += 8) {
        int s0 = g_csr[j + 0], s1 = g_csr[j + 1], s2 = g_csr[j + 2], s3 = g_csr[j + 3];
        int s4 = g_csr[j + 4], s5 = g_csr[j + 5], s6 = g_csr[j + 6], s7 = g_csr[j + 7];
        uint2 c0 = x2[s0 * 32 + lane];
        uint2 c1 = x2[s1 * 32 + lane];
        uint2 c2 = x2[s2 * 32 + lane];
        uint2 c3 = x2[s3 * 32 + lane];
        uint2 c4 = x2[s4 * 32 + lane];
        uint2 c5 = x2[s5 * 32 + lane];
        uint2 c6 = x2[s6 * 32 + lane];
        uint2 c7 = x2[s7 * 32 + lane];
#define ACC(c)                                                     \
        {                                                          \
            float2 f0 = __half22float2(*(__half2*)&(c).x);         \
            float2 f1 = __half22float2(*(__half2*)&(c).y);         \
            ax += f0.x; ay += f0.y; az += f1.x; aw += f1.y;        \
        }
        ACC(c0) ACC(c1) ACC(c2) ACC(c3) ACC(c4) ACC(c5) ACC(c6) ACC(c7)
    }
    for (; j < end; ++j) {
        int s = g_csr[j];
        uint2 c = x2[s * 32 + lane];
        ACC(c)
    }
#undef ACC

    float4 o;
    if (d > 0) {
        float inv = 1.0f / (float)d;
        o.x = ax * inv; o.y = ay * inv; o.z = az * inv; o.w = aw * inv;
    } else {
        o = ((const float4*)x)[gw * 32 + lane];
    }

    unsigned short h0, h1, h2, h3, l0, l1, l2, l3;
    split_bf16(o.x, h0, l0);
    split_bf16(o.y, h1, l1);
    split_bf16(o.z, h2, l2);
    split_bf16(o.w, h3, l3);
    uint2 hv = make_uint2(((uint32_t)h1 << 16) | h0, ((uint32_t)h3 << 16) | h2);
    uint2 lv = make_uint2(((uint32_t)l1 << 16) | l0, ((uint32_t)l3 << 16) | l2);
    int base = gw * F_IN + lane * 4;
    *(uint2*)&g_hh[base] = hv;
    *(uint2*)&g_hl[base] = lv;
}

// ---------------- mma.sync bf16 GEMM: 512 thr, grid (79,4), warp tile 32x32 --
#define GBM 128
#define APITCH 528
#define A_BYTES (128 * APITCH)
#define GEMM_SMEM_BYTES (2 * A_BYTES + 256)

__device__ __forceinline__ uint32_t smem_u32(const void* p) {
    uint32_t a;
    asm("{ .reg .u64 t; cvta.to.shared.u64 t, %1; cvt.u32.u64 %0, t; }"
        : "=r"(a) : "l"(p));
    return a;
}

#define LDMX4(r0, r1, r2, r3, addr)                                             \
    asm volatile("ldmatrix.sync.aligned.m8n8.x4.shared.b16 {%0,%1,%2,%3}, [%4];" \
                 : "=r"(r0), "=r"(r1), "=r"(r2), "=r"(r3) : "r"(addr))

#define MMA16816(c, a0, a1, a2, a3, b0, b1)                                     \
    asm volatile("mma.sync.aligned.m16n8k16.row.col.f32.bf16.bf16.f32 "         \
                 "{%0,%1,%2,%3}, {%4,%5,%6,%7}, {%8,%9}, {%0,%1,%2,%3};"        \
                 : "+f"((c)[0]), "+f"((c)[1]), "+f"((c)[2]), "+f"((c)[3])       \
                 : "r"(a0), "r"(a1), "r"(a2), "r"(a3), "r"(b0), "r"(b1))

__global__ void __launch_bounds__(512, 1)
k_gemm_mma(const float* __restrict__ bias, float* __restrict__ out) {
    extern __shared__ char smem_raw[];
    uint32_t sb0 = smem_u32(smem_raw);
    uint32_t ab = (sb0 + 255) & ~255u;
    char* tb = smem_raw + (ab - sb0);
    const uint32_t B_OFF = A_BYTES;

    int tid = threadIdx.x;
    int wid = tid >> 5, lane = tid & 31;
    int warp_m = wid & 3;        // 4 warps x 32 rows
    int warp_n = wid >> 2;       // 4 warps x 32 cols
    int m0 = blockIdx.x * GBM;
    int n0 = blockIdx.y * 128;

    // ---- A tile ----
    const uint4* __restrict__ hh4 = (const uint4*)g_hh;
    const uint4* __restrict__ hl4 = (const uint4*)g_hl;
    for (int i = tid; i < 128 * 16; i += 512) {
        int m = i >> 4;
        int c = i & 15;
        uint4 hv, lv;
        if (m0 + m < N_NODES) {
            hv = hh4[(size_t)(m0 + m) * 16 + c];
            lv = hl4[(size_t)(m0 + m) * 16 + c];
        } else {
            hv = make_uint4(0, 0, 0, 0);
            lv = make_uint4(0, 0, 0, 0);
        }
        char* row = tb + m * APITCH + c * 16;
        *(uint4*)(row) = hv;
        *(uint4*)(row + 256) = lv;
    }

    // ---- B tile (this block's 128-col chunk) ----
    const uint4* __restrict__ wh4 = (const uint4*)g_wt_hi;
    const uint4* __restrict__ wl4 = (const uint4*)g_wt_lo;
    for (int i = tid; i < 128 * 16; i += 512) {
        int n = i >> 4;
        int c = i & 15;
        uint4 hv = wh4[(size_t)(n0 + n) * 16 + c];
        uint4 lv = wl4[(size_t)(n0 + n) * 16 + c];
        char* row = tb + B_OFF + n * APITCH + c * 16;
        *(uint4*)(row) = hv;
        *(uint4*)(row + 256) = lv;
    }
    __syncthreads();

    float acc[2][4][4] = {};

    int a_row = (lane & 15);
    int a_koff = (lane >> 4) << 4;
    int b_nrow = ((lane >> 4) << 3) + (lane & 7);
    int b_koff = ((lane >> 3) & 1) << 4;

#pragma unroll
    for (int pass = 0; pass < 3; pass++) {
        uint32_t abase = (pass < 2) ? 0u : 256u;
        uint32_t bbase = (pass == 1) ? 256u : 0u;
#pragma unroll
        for (int kk = 0; kk < 8; kk++) {
            uint32_t kb = kk * 32;
            uint32_t a0, a1, a2, a3, a4, a5, a6, a7;
            {
                uint32_t addr0 = ab + (uint32_t)((warp_m * 32 + a_row) * APITCH) +
                                 abase + kb + a_koff;
                uint32_t addr1 = addr0 + 16 * APITCH;
                LDMX4(a0, a1, a2, a3, addr0);
                LDMX4(a4, a5, a6, a7, addr1);
            }
            // 4 n8 tiles for this warp's 32 cols: 2 LDMX4 (16 rows each)
#pragma unroll
            for (int nt2 = 0; nt2 < 2; nt2++) {
                uint32_t baddr = ab + B_OFF +
                                 (uint32_t)((warp_n * 32 + nt2 * 16 + b_nrow) * APITCH) +
                                 bbase + kb + b_koff;
                uint32_t b0, b1, b2, b3;
                LDMX4(b0, b1, b2, b3, baddr);
                MMA16816(acc[0][nt2 * 2 + 0], a0, a1, a2, a3, b0, b1);
                MMA16816(acc[1][nt2 * 2 + 0], a4, a5, a6, a7, b0, b1);
                MMA16816(acc[0][nt2 * 2 + 1], a0, a1, a2, a3, b2, b3);
                MMA16816(acc[1][nt2 * 2 + 1], a4, a5, a6, a7, b2, b3);
            }
        }
    }

    // ---- epilogue ----
    int g = lane >> 2;
    int t = lane & 3;
#pragma unroll
    for (int mt = 0; mt < 2; mt++) {
        int row0 = m0 + warp_m * 32 + mt * 16 + g;
        int row1 = row0 + 8;
#pragma unroll
        for (int nt = 0; nt < 4; nt++) {
            int col = n0 + warp_n * 32 + nt * 8 + t * 2;
            float2 bv = *(const float2*)&bias[col];
            if (row0 < N_NODES) {
                float2 o = make_float2(acc[mt][nt][0] + bv.x, acc[mt][nt][1] + bv.y);
                *(float2*)&out[(size_t)row0 * F_OUT + col] = o;
            }
            if (row1 < N_NODES) {
                float2 o = make_float2(acc[mt][nt][2] + bv.x, acc[mt][nt][3] + bv.y);
                *(float2*)&out[(size_t)row1 * F_OUT + col] = o;
            }
        }
    }
}

// ---------------- launch ----------------
extern "C" void kernel_launch(void* const* d_in, const int* in_sizes, int n_in,
                              void* d_out, int out_size) {
    const float* x   = (const float*)d_in[0];
    const int*   src = (const int*)d_in[1];
    const int*   dst = (const int*)d_in[2];
    const float* W   = (const float*)d_in[3];
    const float* b   = (const float*)d_in[4];
    float* out = (float*)d_out;

    cudaFuncSetAttribute(k_gemm_mma, cudaFuncAttributeMaxDynamicSharedMemorySize,
                         GEMM_SMEM_BYTES);

    void* degp = nullptr;
    cudaGetSymbolAddress(&degp, g_deg);
    cudaMemsetAsync(degp, 0, N_NODES * sizeof(int));

    k_conv<<<(XCONV_ITEMS + WCONV_ITEMS + 255) / 256, 256>>>(x, W);
    k_deg<<<(N_EDGES / 8 + 255) / 256, 256>>>(dst);
    k_off<<<(N_NODES + 1023) / 1024, 1024>>>();
    k_fill<<<(N_EDGES / 8 + 255) / 256, 256>>>(src, dst);
    k_gather<<<(N_NODES * 32 + 255) / 256, 256>>>(x);
    dim3 gg((N_NODES + GBM - 1) / GBM, F_OUT / 128);
    k_gemm_mma<<<gg, 512, GEMM_SMEM_BYTES>>>(b, out);
}

// round 14
// speedup vs baseline: 1.1599x; 1.0418x over previous
#include <cuda_runtime.h>
#include <cuda_bf16.h>
#include <cuda_fp16.h>
#include <cstdint>

#define N_NODES 10000
#define N_EDGES 640000
#define F_IN    128
#define F_OUT   512

// ---------------- device scratch ----------------
__device__ int   g_deg[N_NODES + 1];     // [N_NODES] = allocation cursor
__device__ int   g_off[N_NODES];
__device__ int   g_rank[N_EDGES];
__device__ int   g_csr[N_EDGES];
__device__ __align__(16) __half g_x16[N_NODES * F_IN];
__device__ __align__(16) unsigned short g_hh[N_NODES * F_IN];
__device__ __align__(16) unsigned short g_hl[N_NODES * F_IN];
__device__ __align__(16) unsigned short g_wt_hi[F_OUT * F_IN];
__device__ __align__(16) unsigned short g_wt_lo[F_OUT * F_IN];

// PDL primitives (sm_90+; legal under compute_100)
#define GDC_WAIT()   asm volatile("griddepcontrol.wait;" ::: "memory")
#define GDC_TRIG()   asm volatile("griddepcontrol.launch_dependents;" ::: "memory")

__device__ __forceinline__ void split_bf16(float v, unsigned short& h, unsigned short& l) {
    __nv_bfloat16 bh = __float2bfloat16(v);
    __nv_bfloat16 bl = __float2bfloat16(v - __bfloat162float(bh));
    h = __bfloat16_as_ushort(bh);
    l = __bfloat16_as_ushort(bl);
}

// ---------------- fused conversions ----------------
#define XCONV_ITEMS (N_NODES * F_IN / 4)
#define WCONV_ITEMS (F_OUT * F_IN)
__global__ void k_conv(const float* __restrict__ x, const float* __restrict__ W) {
    int i = blockIdx.x * blockDim.x + threadIdx.x;
    if (i < XCONV_ITEMS) {
        float4 v = ((const float4*)x)[i];
        __half2 a = __floats2half2_rn(v.x, v.y);
        __half2 b = __floats2half2_rn(v.z, v.w);
        ((uint2*)g_x16)[i] = make_uint2(*(uint32_t*)&a, *(uint32_t*)&b);
    } else {
        int idx = i - XCONV_ITEMS;
        if (idx < WCONV_ITEMS) {
            int n = idx >> 7, k = idx & 127;
            float v = W[(size_t)k * F_OUT + n];
            unsigned short h, l;
            split_bf16(v, h, l);
            g_wt_hi[idx] = h;
            g_wt_lo[idx] = l;
        }
    }
    GDC_TRIG();
}

// ---------------- deg + rank (8 edges/thread) ----------------
__global__ void k_deg(const int* __restrict__ dst) {
    GDC_WAIT();
    int t = blockIdx.x * blockDim.x + threadIdx.x;
    int e = t * 8;
    if (e < N_EDGES) {
        int4 a = *(const int4*)&dst[e];
        int4 b = *(const int4*)&dst[e + 4];
        int r0 = atomicAdd(&g_deg[a.x], 1);
        int r1 = atomicAdd(&g_deg[a.y], 1);
        int r2 = atomicAdd(&g_deg[a.z], 1);
        int r3 = atomicAdd(&g_deg[a.w], 1);
        int r4 = atomicAdd(&g_deg[b.x], 1);
        int r5 = atomicAdd(&g_deg[b.y], 1);
        int r6 = atomicAdd(&g_deg[b.z], 1);
        int r7 = atomicAdd(&g_deg[b.w], 1);
        *(int4*)&g_rank[e]     = make_int4(r0, r1, r2, r3);
        *(int4*)&g_rank[e + 4] = make_int4(r4, r5, r6, r7);
    }
    GDC_TRIG();
}

// ---------------- segment allocation (warp-aggregated cursor) ----------------
__global__ void k_off() {
    GDC_WAIT();
    int i = blockIdx.x * blockDim.x + threadIdx.x;
    int lane = threadIdx.x & 31;
    int d = (i < N_NODES) ? g_deg[i] : 0;
    int inc = d;
#pragma unroll
    for (int o = 1; o < 32; o <<= 1) {
        int v = __shfl_up_sync(~0u, inc, o);
        if (lane >= o) inc += v;
    }
    int wsum = __shfl_sync(~0u, inc, 31);
    int base = 0;
    if (lane == 31) base = atomicAdd(&g_deg[N_NODES], wsum);
    base = __shfl_sync(~0u, base, 31);
    if (i < N_NODES) g_off[i] = base + inc - d;
    GDC_TRIG();
}

// ---------------- fill CSR (atomic-free, 8 edges/thread) ---------------------
__global__ void k_fill(const int* __restrict__ src, const int* __restrict__ dst) {
    GDC_WAIT();
    int t = blockIdx.x * blockDim.x + threadIdx.x;
    int e = t * 8;
    if (e < N_EDGES) {
        int4 da = *(const int4*)&dst[e];
        int4 db = *(const int4*)&dst[e + 4];
        int4 sa = *(const int4*)&src[e];
        int4 sb = *(const int4*)&src[e + 4];
        int4 ra = *(const int4*)&g_rank[e];
        int4 rb = *(const int4*)&g_rank[e + 4];
        g_csr[g_off[da.x] + ra.x] = sa.x;
        g_csr[g_off[da.y] + ra.y] = sa.y;
        g_csr[g_off[da.z] + ra.z] = sa.z;
        g_csr[g_off[da.w] + ra.w] = sa.w;
        g_csr[g_off[db.x] + rb.x] = sb.x;
        g_csr[g_off[db.y] + rb.y] = sb.y;
        g_csr[g_off[db.z] + rb.z] = sb.z;
        g_csr[g_off[db.w] + rb.w] = sb.w;
    }
    GDC_TRIG();
}

// ---------------- gather-mean (fp16 reads) -> bf16 hi/lo rows ----------------
__global__ void k_gather(const float* __restrict__ x) {
    GDC_WAIT();
    int gw = (blockIdx.x * blockDim.x + threadIdx.x) >> 5;
    int lane = threadIdx.x & 31;
    if (gw < N_NODES) {
        const uint2* __restrict__ x2 = (const uint2*)g_x16;
        int d = g_deg[gw];
        int beg = g_off[gw];
        int end = beg + d;

        float ax = 0.f, ay = 0.f, az = 0.f, aw = 0.f;
        int j = beg;
        for (; j + 7 < end; j += 8) {
            int s0 = g_csr[j + 0], s1 = g_csr[j + 1], s2 = g_csr[j + 2], s3 = g_csr[j + 3];
            int s4 = g_csr[j + 4], s5 = g_csr[j + 5], s6 = g_csr[j + 6], s7 = g_csr[j + 7];
            uint2 c0 = x2[s0 * 32 + lane];
            uint2 c1 = x2[s1 * 32 + lane];
            uint2 c2 = x2[s2 * 32 + lane];
            uint2 c3 = x2[s3 * 32 + lane];
            uint2 c4 = x2[s4 * 32 + lane];
            uint2 c5 = x2[s5 * 32 + lane];
            uint2 c6 = x2[s6 * 32 + lane];
            uint2 c7 = x2[s7 * 32 + lane];
#define ACC(c)                                                     \
            {                                                      \
                float2 f0 = __half22float2(*(__half2*)&(c).x);     \
                float2 f1 = __half22float2(*(__half2*)&(c).y);     \
                ax += f0.x; ay += f0.y; az += f1.x; aw += f1.y;    \
            }
            ACC(c0) ACC(c1) ACC(c2) ACC(c3) ACC(c4) ACC(c5) ACC(c6) ACC(c7)
        }
        for (; j < end; ++j) {
            int s = g_csr[j];
            uint2 c = x2[s * 32 + lane];
            ACC(c)
        }
#undef ACC

        float4 o;
        if (d > 0) {
            float inv = 1.0f / (float)d;
            o.x = ax * inv; o.y = ay * inv; o.z = az * inv; o.w = aw * inv;
        } else {
            o = ((const float4*)x)[gw * 32 + lane];   // exact fp32 fallback
        }

        unsigned short h0, h1, h2, h3, l0, l1, l2, l3;
        split_bf16(o.x, h0, l0);
        split_bf16(o.y, h1, l1);
        split_bf16(o.z, h2, l2);
        split_bf16(o.w, h3, l3);
        uint2 hv = make_uint2(((uint32_t)h1 << 16) | h0, ((uint32_t)h3 << 16) | h2);
        uint2 lv = make_uint2(((uint32_t)l1 << 16) | l0, ((uint32_t)l3 << 16) | l2);
        int base = gw * F_IN + lane * 4;
        *(uint2*)&g_hh[base] = hv;
        *(uint2*)&g_hl[base] = lv;
    }
    GDC_TRIG();
}

// ---------------- mma.sync bf16 GEMM: 512 thr, grid (79,4), warp tile 32x32 --
#define GBM 128
#define APITCH 528
#define A_BYTES (128 * APITCH)
#define GEMM_SMEM_BYTES (2 * A_BYTES + 256)

__device__ __forceinline__ uint32_t smem_u32(const void* p) {
    uint32_t a;
    asm("{ .reg .u64 t; cvta.to.shared.u64 t, %1; cvt.u32.u64 %0, t; }"
        : "=r"(a) : "l"(p));
    return a;
}

#define LDMX4(r0, r1, r2, r3, addr)                                             \
    asm volatile("ldmatrix.sync.aligned.m8n8.x4.shared.b16 {%0,%1,%2,%3}, [%4];" \
                 : "=r"(r0), "=r"(r1), "=r"(r2), "=r"(r3) : "r"(addr))

#define MMA16816(c, a0, a1, a2, a3, b0, b1)                                     \
    asm volatile("mma.sync.aligned.m16n8k16.row.col.f32.bf16.bf16.f32 "         \
                 "{%0,%1,%2,%3}, {%4,%5,%6,%7}, {%8,%9}, {%0,%1,%2,%3};"        \
                 : "+f"((c)[0]), "+f"((c)[1]), "+f"((c)[2]), "+f"((c)[3])       \
                 : "r"(a0), "r"(a1), "r"(a2), "r"(a3), "r"(b0), "r"(b1))

__global__ void __launch_bounds__(512, 1)
k_gemm_mma(const float* __restrict__ bias, float* __restrict__ out) {
    extern __shared__ char smem_raw[];
    uint32_t sb0 = smem_u32(smem_raw);
    uint32_t ab = (sb0 + 255) & ~255u;
    char* tb = smem_raw + (ab - sb0);
    const uint32_t B_OFF = A_BYTES;

    int tid = threadIdx.x;
    int wid = tid >> 5, lane = tid & 31;
    int warp_m = wid & 3;
    int warp_n = wid >> 2;
    int m0 = blockIdx.x * GBM;
    int n0 = blockIdx.y * 128;

    // ---- B tile FIRST (depends only on k_conv, long finished) — overlaps
    //      the gather tail thanks to PDL early launch ----
    const uint4* __restrict__ wh4 = (const uint4*)g_wt_hi;
    const uint4* __restrict__ wl4 = (const uint4*)g_wt_lo;
    for (int i = tid; i < 128 * 16; i += 512) {
        int n = i >> 4;
        int c = i & 15;
        uint4 hv = wh4[(size_t)(n0 + n) * 16 + c];
        uint4 lv = wl4[(size_t)(n0 + n) * 16 + c];
        char* row = tb + B_OFF + n * APITCH + c * 16;
        *(uint4*)(row) = hv;
        *(uint4*)(row + 256) = lv;
    }

    GDC_WAIT();   // now gather's g_hh/g_hl are visible

    // ---- A tile ----
    const uint4* __restrict__ hh4 = (const uint4*)g_hh;
    const uint4* __restrict__ hl4 = (const uint4*)g_hl;
    for (int i = tid; i < 128 * 16; i += 512) {
        int m = i >> 4;
        int c = i & 15;
        uint4 hv, lv;
        if (m0 + m < N_NODES) {
            hv = hh4[(size_t)(m0 + m) * 16 + c];
            lv = hl4[(size_t)(m0 + m) * 16 + c];
        } else {
            hv = make_uint4(0, 0, 0, 0);
            lv = make_uint4(0, 0, 0, 0);
        }
        char* row = tb + m * APITCH + c * 16;
        *(uint4*)(row) = hv;
        *(uint4*)(row + 256) = lv;
    }
    __syncthreads();

    float acc[2][4][4] = {};

    int a_row = (lane & 15);
    int a_koff = (lane >> 4) << 4;
    int b_nrow = ((lane >> 4) << 3) + (lane & 7);
    int b_koff = ((lane >> 3) & 1) << 4;

#pragma unroll
    for (int pass = 0; pass < 3; pass++) {
        uint32_t abase = (pass < 2) ? 0u : 256u;
        uint32_t bbase = (pass == 1) ? 256u : 0u;
#pragma unroll
        for (int kk = 0; kk < 8; kk++) {
            uint32_t kb = kk * 32;
            uint32_t a0, a1, a2, a3, a4, a5, a6, a7;
            {
                uint32_t addr0 = ab + (uint32_t)((warp_m * 32 + a_row) * APITCH) +
                                 abase + kb + a_koff;
                uint32_t addr1 = addr0 + 16 * APITCH;
                LDMX4(a0, a1, a2, a3, addr0);
                LDMX4(a4, a5, a6, a7, addr1);
            }
#pragma unroll
            for (int nt2 = 0; nt2 < 2; nt2++) {
                uint32_t baddr = ab + B_OFF +
                                 (uint32_t)((warp_n * 32 + nt2 * 16 + b_nrow) * APITCH) +
                                 bbase + kb + b_koff;
                uint32_t b0, b1, b2, b3;
                LDMX4(b0, b1, b2, b3, baddr);
                MMA16816(acc[0][nt2 * 2 + 0], a0, a1, a2, a3, b0, b1);
                MMA16816(acc[1][nt2 * 2 + 0], a4, a5, a6, a7, b0, b1);
                MMA16816(acc[0][nt2 * 2 + 1], a0, a1, a2, a3, b2, b3);
                MMA16816(acc[1][nt2 * 2 + 1], a4, a5, a6, a7, b2, b3);
            }
        }
    }

    int g = lane >> 2;
    int t = lane & 3;
#pragma unroll
    for (int mt = 0; mt < 2; mt++) {
        int row0 = m0 + warp_m * 32 + mt * 16 + g;
        int row1 = row0 + 8;
#pragma unroll
        for (int nt = 0; nt < 4; nt++) {
            int col = n0 + warp_n * 32 + nt * 8 + t * 2;
            float2 bv = *(const float2*)&bias[col];
            if (row0 < N_NODES) {
                float2 o = make_float2(acc[mt][nt][0] + bv.x, acc[mt][nt][1] + bv.y);
                *(float2*)&out[(size_t)row0 * F_OUT + col] = o;
            }
            if (row1 < N_NODES) {
                float2 o = make_float2(acc[mt][nt][2] + bv.x, acc[mt][nt][3] + bv.y);
                *(float2*)&out[(size_t)row1 * F_OUT + col] = o;
            }
        }
    }
}

// ---------------- launch (PDL-chained) ----------------
static void launch_pdl(void* fn, dim3 grid, dim3 block, size_t smem,
                       void** args) {
    cudaLaunchAttribute attr[1];
    attr[0].id = cudaLaunchAttributeProgrammaticStreamSerialization;
    attr[0].val.programmaticStreamSerializationAllowed = 1;
    cudaLaunchConfig_t cfg = {};
    cfg.gridDim = grid;
    cfg.blockDim = block;
    cfg.dynamicSmemBytes = smem;
    cfg.stream = 0;
    cfg.attrs = attr;
    cfg.numAttrs = 1;
    cudaLaunchKernelExC(&cfg, fn, args);
}

extern "C" void kernel_launch(void* const* d_in, const int* in_sizes, int n_in,
                              void* d_out, int out_size) {
    const float* x   = (const float*)d_in[0];
    const int*   src = (const int*)d_in[1];
    const int*   dst = (const int*)d_in[2];
    const float* W   = (const float*)d_in[3];
    const float* b   = (const float*)d_in[4];
    float* out = (float*)d_out;

    cudaFuncSetAttribute(k_gemm_mma, cudaFuncAttributeMaxDynamicSharedMemorySize,
                         GEMM_SMEM_BYTES);

    // zeroes deg AND the allocation cursor (g_deg[N_NODES])
    void* degp = nullptr;
    cudaGetSymbolAddress(&degp, g_deg);
    cudaMemsetAsync(degp, 0, (N_NODES + 1) * sizeof(int));

    k_conv<<<(XCONV_ITEMS + WCONV_ITEMS + 255) / 256, 256>>>(x, W);

    {   // k_deg
        void* args[] = {(void*)&dst};
        launch_pdl((void*)k_deg, dim3((N_EDGES / 8 + 255) / 256), dim3(256), 0, args);
    }
    {   // k_off
        void* args[] = {};
        launch_pdl((void*)k_off, dim3((N_NODES + 1023) / 1024), dim3(1024), 0, args);
    }
    {   // k_fill
        void* args[] = {(void*)&src, (void*)&dst};
        launch_pdl((void*)k_fill, dim3((N_EDGES / 8 + 255) / 256), dim3(256), 0, args);
    }
    {   // k_gather
        void* args[] = {(void*)&x};
        launch_pdl((void*)k_gather, dim3((N_NODES * 32 + 255) / 256), dim3(256), 0, args);
    }
    {   // k_gemm_mma
        void* args[] = {(void*)&b, (void*)&out};
        launch_pdl((void*)k_gemm_mma, dim3((N_NODES + GBM - 1) / GBM, F_OUT / 128),
                   dim3(512), GEMM_SMEM_BYTES, args);
    }
}